// round 2
// baseline (speedup 1.0000x reference)
#include <cuda_runtime.h>
#include <math.h>

#define BB     8
#define M_TOT  1026
#define CC     384
#define N1     513
#define HH     6
#define DD     64
#define BHN    (BB*HH)      // 48
#define MROWS  (BB*N1)      // 4104
#define MROWS2 (BB*M_TOT)   // 8208

// ---- scratch (device globals; no cudaMalloc allowed) ----
__device__ int   g_sel;
__device__ float g_Q [MROWS*CC];
__device__ float g_K [MROWS*CC];
__device__ float g_V1[MROWS*CC];
__device__ float g_V2[MROWS*CC];
__device__ float g_S [(size_t)BHN*N1*N1];   // ~50.5 MB
__device__ float g_O [MROWS2*CC];           // pre-Wo activations

// ------------------------------------------------------------------
// 0) straight-through gumbel selection: argmax(weights + noise)
// ------------------------------------------------------------------
__global__ void select_kernel(const float* __restrict__ w,
                              const float* __restrict__ g) {
    float best = w[0] + g[0];
    int bi = 0;
    #pragma unroll
    for (int i = 1; i < 4; i++) {
        float v = w[i] + g[i];
        if (v > best) { best = v; bi = i; }
    }
    g_sel = bi;
}

// ------------------------------------------------------------------
// 1) input projections: Q (selected), K (selected), V1, V2
//    batched via blockIdx.z; GEMM (4104 x 384 x 384), BM=128 BN=64 BK=32
// ------------------------------------------------------------------
__global__ __launch_bounds__(256)
void proj_kernel(const float* __restrict__ x,
                 const float* Wq1, const float* bq1,
                 const float* Wq2, const float* bq2,
                 const float* Wk1, const float* bk1,
                 const float* Wk2, const float* bk2,
                 const float* Wv1, const float* bv1,
                 const float* Wv2, const float* bv2) {
    const int job = blockIdx.z;
    const int sel = g_sel;
    const float* W; const float* bias; float* OUT; int off;
    if (job == 0) { int qs = sel >> 1; W = qs ? Wq2 : Wq1; bias = qs ? bq2 : bq1; OUT = g_Q;  off = qs ? N1 : 0; }
    else if (job == 1) { int ks = sel & 1; W = ks ? Wk2 : Wk1; bias = ks ? bk2 : bk1; OUT = g_K;  off = ks ? N1 : 0; }
    else if (job == 2) { W = Wv1; bias = bv1; OUT = g_V1; off = 0;  }
    else               { W = Wv2; bias = bv2; OUT = g_V2; off = N1; }

    __shared__ float As[32][132];   // As[k][m], pad to 132 (16B aligned rows)
    __shared__ float Bs[32][64];

    const int m0 = blockIdx.y * 128, n0 = blockIdx.x * 64;
    const int tid = threadIdx.x;
    const int ty = tid >> 4, tx = tid & 15;
    float acc[8][4];
    #pragma unroll
    for (int i = 0; i < 8; i++)
        #pragma unroll
        for (int j = 0; j < 4; j++) acc[i][j] = 0.f;

    for (int k0 = 0; k0 < CC; k0 += 32) {
        // A tile: 128x32 (x rows, with batch skip mapping), coalesced 128B rows
        #pragma unroll
        for (int t = 0; t < 16; t++) {
            int idx = tid + t * 256;
            int mm = idx >> 5, kk = idx & 31;
            int m = m0 + mm;
            float v = 0.f;
            if (m < MROWS) {
                int b = m / N1, n = m % N1;
                v = x[((size_t)b * M_TOT + n + off) * CC + k0 + kk];
            }
            As[kk][mm] = v;
        }
        // B tile: 32x64 from W
        #pragma unroll
        for (int t = 0; t < 8; t++) {
            int idx = tid + t * 256;
            int kk = idx >> 6, nn = idx & 63;
            Bs[kk][nn] = W[(k0 + kk) * CC + n0 + nn];
        }
        __syncthreads();
        #pragma unroll
        for (int kk = 0; kk < 32; kk++) {
            float a[8], bb[4];
            #pragma unroll
            for (int i = 0; i < 8; i++) a[i] = As[kk][ty * 8 + i];
            #pragma unroll
            for (int j = 0; j < 4; j++) bb[j] = Bs[kk][tx * 4 + j];
            #pragma unroll
            for (int i = 0; i < 8; i++)
                #pragma unroll
                for (int j = 0; j < 4; j++) acc[i][j] += a[i] * bb[j];
        }
        __syncthreads();
    }
    #pragma unroll
    for (int i = 0; i < 8; i++) {
        int m = m0 + ty * 8 + i;
        if (m >= MROWS) continue;
        #pragma unroll
        for (int j = 0; j < 4; j++) {
            int n = n0 + tx * 4 + j;
            OUT[(size_t)m * CC + n] = acc[i][j] + bias[n];
        }
    }
}

// ------------------------------------------------------------------
// 2) scores: S[bh][i][j] = scale * dot(Q[b,i,h,:], K[b,j,h,:])  (d=64)
//    BM=BN=64, BK=64 (full d). Transposed smem tiles.
// ------------------------------------------------------------------
__global__ __launch_bounds__(256)
void scores_kernel() {
    const int bh = blockIdx.z;
    const int b = bh / HH, hh = bh % HH;
    const int i0 = blockIdx.y * 64, j0 = blockIdx.x * 64;

    __shared__ float Qs[64][68];   // Qs[d][i]
    __shared__ float Ks[64][68];   // Ks[d][j]

    const int tid = threadIdx.x;
    const int ty = tid >> 4, tx = tid & 15;

    #pragma unroll
    for (int t = 0; t < 16; t++) {
        int idx = tid + t * 256;
        int r = idx >> 6, c = idx & 63;
        int qi = i0 + r;
        Qs[c][r] = (qi < N1) ? g_Q[((size_t)b * N1 + qi) * CC + hh * DD + c] : 0.f;
        int kj = j0 + r;
        Ks[c][r] = (kj < N1) ? g_K[((size_t)b * N1 + kj) * CC + hh * DD + c] : 0.f;
    }
    __syncthreads();

    float acc[4][4];
    #pragma unroll
    for (int i = 0; i < 4; i++)
        #pragma unroll
        for (int j = 0; j < 4; j++) acc[i][j] = 0.f;

    #pragma unroll
    for (int kk = 0; kk < 64; kk++) {
        float a[4], bb[4];
        #pragma unroll
        for (int i = 0; i < 4; i++) a[i] = Qs[kk][ty * 4 + i];
        #pragma unroll
        for (int j = 0; j < 4; j++) bb[j] = Ks[kk][tx * 4 + j];
        #pragma unroll
        for (int i = 0; i < 4; i++)
            #pragma unroll
            for (int j = 0; j < 4; j++) acc[i][j] += a[i] * bb[j];
    }

    const float scale = 0.125f;  // 64^-0.5
    const size_t base = (size_t)bh * N1 * N1;
    #pragma unroll
    for (int i = 0; i < 4; i++) {
        int qi = i0 + ty * 4 + i;
        if (qi >= N1) continue;
        #pragma unroll
        for (int j = 0; j < 4; j++) {
            int kj = j0 + tx * 4 + j;
            if (kj >= N1) continue;
            g_S[base + (size_t)qi * N1 + kj] = acc[i][j] * scale;
        }
    }
}

// ------------------------------------------------------------------
// 3) row softmax over 513 elements; one block (128 thr) per row
// ------------------------------------------------------------------
__global__ __launch_bounds__(128)
void softmax_kernel() {
    float* p = g_S + (size_t)blockIdx.x * N1;
    const int t = threadIdx.x;
    __shared__ float red[4];
    __shared__ float red2[4];

    float m = -1e30f;
    for (int j = t; j < N1; j += 128) m = fmaxf(m, p[j]);
    #pragma unroll
    for (int o = 16; o > 0; o >>= 1) m = fmaxf(m, __shfl_xor_sync(0xffffffffu, m, o));
    if ((t & 31) == 0) red[t >> 5] = m;
    __syncthreads();
    m = fmaxf(fmaxf(red[0], red[1]), fmaxf(red[2], red[3]));

    float s = 0.f;
    for (int j = t; j < N1; j += 128) {
        float e = __expf(p[j] - m);
        p[j] = e;
        s += e;
    }
    #pragma unroll
    for (int o = 16; o > 0; o >>= 1) s += __shfl_xor_sync(0xffffffffu, s, o);
    if ((t & 31) == 0) red2[t >> 5] = s;
    __syncthreads();
    s = red2[0] + red2[1] + red2[2] + red2[3];
    const float inv = 1.f / s;
    for (int j = t; j < N1; j += 128) p[j] *= inv;
}

// ------------------------------------------------------------------
// 4) AV: per (b,h): A(513x513) @ [V1|V2](513x128) -> g_O with row split
//    BM=64, BN=128 (full), BK=32
// ------------------------------------------------------------------
__global__ __launch_bounds__(256)
void av_kernel() {
    const int bh = blockIdx.z;
    const int b = bh / HH, hh = bh % HH;
    const int q0 = blockIdx.x * 64;

    __shared__ float As[32][68];    // As[k][q]
    __shared__ float Vs[32][128];   // Vs[k][j]  (j<64: V1, j>=64: V2)

    const int tid = threadIdx.x;
    const int ty = tid >> 4, tx = tid & 15;
    const size_t Sbase = (size_t)bh * N1 * N1;

    float acc[4][8];
    #pragma unroll
    for (int i = 0; i < 4; i++)
        #pragma unroll
        for (int j = 0; j < 8; j++) acc[i][j] = 0.f;

    for (int k0 = 0; k0 < N1; k0 += 32) {
        #pragma unroll
        for (int t = 0; t < 8; t++) {
            int idx = tid + t * 256;
            int q = idx >> 5, kk = idx & 31;
            int qi = q0 + q, ki = k0 + kk;
            As[kk][q] = (qi < N1 && ki < N1) ? g_S[Sbase + (size_t)qi * N1 + ki] : 0.f;
        }
        #pragma unroll
        for (int t = 0; t < 16; t++) {
            int idx = tid + t * 256;
            int kk = idx >> 7, j = idx & 127;
            int ki = k0 + kk;
            float v = 0.f;
            if (ki < N1) {
                if (j < 64) v = g_V1[((size_t)b * N1 + ki) * CC + hh * DD + j];
                else        v = g_V2[((size_t)b * N1 + ki) * CC + hh * DD + (j - 64)];
            }
            Vs[kk][j] = v;
        }
        __syncthreads();
        #pragma unroll
        for (int kk = 0; kk < 32; kk++) {
            float a[4], bb[8];
            #pragma unroll
            for (int i = 0; i < 4; i++) a[i] = As[kk][ty * 4 + i];
            #pragma unroll
            for (int j = 0; j < 8; j++) bb[j] = Vs[kk][tx * 8 + j];
            #pragma unroll
            for (int i = 0; i < 4; i++)
                #pragma unroll
                for (int j = 0; j < 8; j++) acc[i][j] += a[i] * bb[j];
        }
        __syncthreads();
    }

    #pragma unroll
    for (int i = 0; i < 4; i++) {
        int qi = q0 + ty * 4 + i;
        if (qi >= N1) continue;
        #pragma unroll
        for (int j = 0; j < 8; j++) {
            int jj = tx * 8 + j;
            int n = (jj < 64) ? qi : (N1 + qi);
            int c = hh * DD + (jj & 63);
            g_O[((size_t)b * M_TOT + n) * CC + c] = acc[i][j];
        }
    }
}

// ------------------------------------------------------------------
// 5) output projection: out = g_O (8208x384) @ Wo + bo
// ------------------------------------------------------------------
__global__ __launch_bounds__(256)
void final_kernel(const float* __restrict__ Wo,
                  const float* __restrict__ bo,
                  float* __restrict__ out) {
    __shared__ float As[32][132];
    __shared__ float Bs[32][64];

    const int m0 = blockIdx.y * 128, n0 = blockIdx.x * 64;
    const int tid = threadIdx.x;
    const int ty = tid >> 4, tx = tid & 15;
    float acc[8][4];
    #pragma unroll
    for (int i = 0; i < 8; i++)
        #pragma unroll
        for (int j = 0; j < 4; j++) acc[i][j] = 0.f;

    for (int k0 = 0; k0 < CC; k0 += 32) {
        #pragma unroll
        for (int t = 0; t < 16; t++) {
            int idx = tid + t * 256;
            int mm = idx >> 5, kk = idx & 31;
            int m = m0 + mm;
            As[kk][mm] = (m < MROWS2) ? g_O[(size_t)m * CC + k0 + kk] : 0.f;
        }
        #pragma unroll
        for (int t = 0; t < 8; t++) {
            int idx = tid + t * 256;
            int kk = idx >> 6, nn = idx & 63;
            Bs[kk][nn] = Wo[(k0 + kk) * CC + n0 + nn];
        }
        __syncthreads();
        #pragma unroll
        for (int kk = 0; kk < 32; kk++) {
            float a[8], bb[4];
            #pragma unroll
            for (int i = 0; i < 8; i++) a[i] = As[kk][ty * 8 + i];
            #pragma unroll
            for (int j = 0; j < 4; j++) bb[j] = Bs[kk][tx * 4 + j];
            #pragma unroll
            for (int i = 0; i < 8; i++)
                #pragma unroll
                for (int j = 0; j < 4; j++) acc[i][j] += a[i] * bb[j];
        }
        __syncthreads();
    }
    #pragma unroll
    for (int i = 0; i < 8; i++) {
        int m = m0 + ty * 8 + i;
        if (m >= MROWS2) continue;
        #pragma unroll
        for (int j = 0; j < 4; j++) {
            int n = n0 + tx * 4 + j;
            out[(size_t)m * CC + n] = acc[i][j] + bo[n];
        }
    }
}

// ------------------------------------------------------------------
extern "C" void kernel_launch(void* const* d_in, const int* in_sizes, int n_in,
                              void* d_out, int out_size) {
    const float* x   = (const float*)d_in[0];
    const float* Wq1 = (const float*)d_in[1];  const float* bq1 = (const float*)d_in[2];
    const float* Wq2 = (const float*)d_in[3];  const float* bq2 = (const float*)d_in[4];
    const float* Wk1 = (const float*)d_in[5];  const float* bk1 = (const float*)d_in[6];
    const float* Wk2 = (const float*)d_in[7];  const float* bk2 = (const float*)d_in[8];
    const float* Wv1 = (const float*)d_in[9];  const float* bv1 = (const float*)d_in[10];
    const float* Wv2 = (const float*)d_in[11]; const float* bv2 = (const float*)d_in[12];
    const float* Wo  = (const float*)d_in[13]; const float* bo  = (const float*)d_in[14];
    const float* wts = (const float*)d_in[15]; const float* gum = (const float*)d_in[16];
    float* out = (float*)d_out;

    select_kernel<<<1, 1>>>(wts, gum);

    dim3 pg(CC / 64, (MROWS + 127) / 128, 4);               // 6 x 33 x 4
    proj_kernel<<<pg, 256>>>(x, Wq1, bq1, Wq2, bq2, Wk1, bk1, Wk2, bk2,
                             Wv1, bv1, Wv2, bv2);

    dim3 sg((N1 + 63) / 64, (N1 + 63) / 64, BHN);           // 9 x 9 x 48
    scores_kernel<<<sg, 256>>>();

    softmax_kernel<<<BHN * N1, 128>>>();

    av_kernel<<<dim3((N1 + 63) / 64, 1, BHN), 256>>>();     // 9 x 1 x 48

    final_kernel<<<dim3(CC / 64, (MROWS2 + 127) / 128, 1), 256>>>(Wo, bo, out);
}

// round 3
// speedup vs baseline: 1.5713x; 1.5713x over previous
#include <cuda_runtime.h>
#include <math.h>

#define BB     8
#define M_TOT  1026
#define CC     384
#define N1     513
#define HH     6
#define DD     64
#define BHN    (BB*HH)      // 48
#define MROWS  (BB*N1)      // 4104
#define MROWS2 (BB*M_TOT)   // 8208

// ---- scratch (device globals; no cudaMalloc allowed) ----
__device__ int   g_sel;
__device__ float g_Q [MROWS*CC];
__device__ float g_K [MROWS*CC];
__device__ float g_V1[MROWS*CC];
__device__ float g_V2[MROWS*CC];
__device__ float g_S [(size_t)BHN*N1*N1];   // ~50.5 MB
__device__ float g_O [MROWS2*CC];           // pre-Wo activations

// ------------------------------------------------------------------
// 0) straight-through gumbel selection: argmax(weights + noise)
// ------------------------------------------------------------------
__global__ void select_kernel(const float* __restrict__ w,
                              const float* __restrict__ g) {
    float best = w[0] + g[0];
    int bi = 0;
    #pragma unroll
    for (int i = 1; i < 4; i++) {
        float v = w[i] + g[i];
        if (v > best) { best = v; bi = i; }
    }
    g_sel = bi;
}

// ------------------------------------------------------------------
// 1) input projections: Q (selected), K (selected), V1, V2
//    batched via blockIdx.z; GEMM (4104 x 384 x 384), BM=128 BN=64 BK=32
// ------------------------------------------------------------------
__global__ __launch_bounds__(256)
void proj_kernel(const float* __restrict__ x,
                 const float* Wq1, const float* bq1,
                 const float* Wq2, const float* bq2,
                 const float* Wk1, const float* bk1,
                 const float* Wk2, const float* bk2,
                 const float* Wv1, const float* bv1,
                 const float* Wv2, const float* bv2) {
    const int job = blockIdx.z;
    const int sel = g_sel;
    const float* W; const float* bias; float* OUT; int off;
    if (job == 0) { int qs = sel >> 1; W = qs ? Wq2 : Wq1; bias = qs ? bq2 : bq1; OUT = g_Q;  off = qs ? N1 : 0; }
    else if (job == 1) { int ks = sel & 1; W = ks ? Wk2 : Wk1; bias = ks ? bk2 : bk1; OUT = g_K;  off = ks ? N1 : 0; }
    else if (job == 2) { W = Wv1; bias = bv1; OUT = g_V1; off = 0;  }
    else               { W = Wv2; bias = bv2; OUT = g_V2; off = N1; }

    __shared__ float As[32][132];   // As[k][m], pad to 132 (16B aligned rows)
    __shared__ float Bs[32][64];

    const int m0 = blockIdx.y * 128, n0 = blockIdx.x * 64;
    const int tid = threadIdx.x;
    const int ty = tid >> 4, tx = tid & 15;
    float acc[8][4];
    #pragma unroll
    for (int i = 0; i < 8; i++)
        #pragma unroll
        for (int j = 0; j < 4; j++) acc[i][j] = 0.f;

    for (int k0 = 0; k0 < CC; k0 += 32) {
        // A tile: 128x32 (x rows, with batch skip mapping), coalesced 128B rows
        #pragma unroll
        for (int t = 0; t < 16; t++) {
            int idx = tid + t * 256;
            int mm = idx >> 5, kk = idx & 31;
            int m = m0 + mm;
            float v = 0.f;
            if (m < MROWS) {
                int b = m / N1, n = m % N1;
                v = x[((size_t)b * M_TOT + n + off) * CC + k0 + kk];
            }
            As[kk][mm] = v;
        }
        // B tile: 32x64 from W
        #pragma unroll
        for (int t = 0; t < 8; t++) {
            int idx = tid + t * 256;
            int kk = idx >> 6, nn = idx & 63;
            Bs[kk][nn] = W[(k0 + kk) * CC + n0 + nn];
        }
        __syncthreads();
        #pragma unroll
        for (int kk = 0; kk < 32; kk++) {
            float a[8], bb[4];
            #pragma unroll
            for (int i = 0; i < 8; i++) a[i] = As[kk][ty * 8 + i];
            #pragma unroll
            for (int j = 0; j < 4; j++) bb[j] = Bs[kk][tx * 4 + j];
            #pragma unroll
            for (int i = 0; i < 8; i++)
                #pragma unroll
                for (int j = 0; j < 4; j++) acc[i][j] += a[i] * bb[j];
        }
        __syncthreads();
    }
    #pragma unroll
    for (int i = 0; i < 8; i++) {
        int m = m0 + ty * 8 + i;
        if (m >= MROWS) continue;
        #pragma unroll
        for (int j = 0; j < 4; j++) {
            int n = n0 + tx * 4 + j;
            OUT[(size_t)m * CC + n] = acc[i][j] + bias[n];
        }
    }
}

// ------------------------------------------------------------------
// 2) scores: S[bh][i][j] = scale * dot(Q[b,i,h,:], K[b,j,h,:])  (d=64)
//    BM=BN=64, BK=64 (full d). Transposed smem tiles.
// ------------------------------------------------------------------
__global__ __launch_bounds__(256)
void scores_kernel() {
    const int bh = blockIdx.z;
    const int b = bh / HH, hh = bh % HH;
    const int i0 = blockIdx.y * 64, j0 = blockIdx.x * 64;

    __shared__ float Qs[64][68];   // Qs[d][i]
    __shared__ float Ks[64][68];   // Ks[d][j]

    const int tid = threadIdx.x;
    const int ty = tid >> 4, tx = tid & 15;

    #pragma unroll
    for (int t = 0; t < 16; t++) {
        int idx = tid + t * 256;
        int r = idx >> 6, c = idx & 63;
        int qi = i0 + r;
        Qs[c][r] = (qi < N1) ? g_Q[((size_t)b * N1 + qi) * CC + hh * DD + c] : 0.f;
        int kj = j0 + r;
        Ks[c][r] = (kj < N1) ? g_K[((size_t)b * N1 + kj) * CC + hh * DD + c] : 0.f;
    }
    __syncthreads();

    float acc[4][4];
    #pragma unroll
    for (int i = 0; i < 4; i++)
        #pragma unroll
        for (int j = 0; j < 4; j++) acc[i][j] = 0.f;

    #pragma unroll
    for (int kk = 0; kk < 64; kk++) {
        float a[4], bb[4];
        #pragma unroll
        for (int i = 0; i < 4; i++) a[i] = Qs[kk][ty * 4 + i];
        #pragma unroll
        for (int j = 0; j < 4; j++) bb[j] = Ks[kk][tx * 4 + j];
        #pragma unroll
        for (int i = 0; i < 4; i++)
            #pragma unroll
            for (int j = 0; j < 4; j++) acc[i][j] += a[i] * bb[j];
    }

    const float scale = 0.125f;  // 64^-0.5
    const size_t base = (size_t)bh * N1 * N1;
    #pragma unroll
    for (int i = 0; i < 4; i++) {
        int qi = i0 + ty * 4 + i;
        if (qi >= N1) continue;
        #pragma unroll
        for (int j = 0; j < 4; j++) {
            int kj = j0 + tx * 4 + j;
            if (kj >= N1) continue;
            g_S[base + (size_t)qi * N1 + kj] = acc[i][j] * scale;
        }
    }
}

// ------------------------------------------------------------------
// 3) row softmax over 513 elements; one block (128 thr) per row
// ------------------------------------------------------------------
__global__ __launch_bounds__(128)
void softmax_kernel() {
    float* p = g_S + (size_t)blockIdx.x * N1;
    const int t = threadIdx.x;
    __shared__ float red[4];
    __shared__ float red2[4];

    float m = -1e30f;
    for (int j = t; j < N1; j += 128) m = fmaxf(m, p[j]);
    #pragma unroll
    for (int o = 16; o > 0; o >>= 1) m = fmaxf(m, __shfl_xor_sync(0xffffffffu, m, o));
    if ((t & 31) == 0) red[t >> 5] = m;
    __syncthreads();
    m = fmaxf(fmaxf(red[0], red[1]), fmaxf(red[2], red[3]));

    float s = 0.f;
    for (int j = t; j < N1; j += 128) {
        float e = __expf(p[j] - m);
        p[j] = e;
        s += e;
    }
    #pragma unroll
    for (int o = 16; o > 0; o >>= 1) s += __shfl_xor_sync(0xffffffffu, s, o);
    if ((t & 31) == 0) red2[t >> 5] = s;
    __syncthreads();
    s = red2[0] + red2[1] + red2[2] + red2[3];
    const float inv = 1.f / s;
    for (int j = t; j < N1; j += 128) p[j] *= inv;
}

// ------------------------------------------------------------------
// 4) AV: per (b,h): A(513x513) @ [V1|V2](513x128) -> g_O with row split
//    BM=64, BN=128 (full), BK=32
// ------------------------------------------------------------------
__global__ __launch_bounds__(256)
void av_kernel() {
    const int bh = blockIdx.z;
    const int b = bh / HH, hh = bh % HH;
    const int q0 = blockIdx.x * 64;

    __shared__ float As[32][68];    // As[k][q]
    __shared__ float Vs[32][128];   // Vs[k][j]  (j<64: V1, j>=64: V2)

    const int tid = threadIdx.x;
    const int ty = tid >> 4, tx = tid & 15;
    const size_t Sbase = (size_t)bh * N1 * N1;

    float acc[4][8];
    #pragma unroll
    for (int i = 0; i < 4; i++)
        #pragma unroll
        for (int j = 0; j < 8; j++) acc[i][j] = 0.f;

    for (int k0 = 0; k0 < N1; k0 += 32) {
        #pragma unroll
        for (int t = 0; t < 8; t++) {
            int idx = tid + t * 256;
            int q = idx >> 5, kk = idx & 31;
            int qi = q0 + q, ki = k0 + kk;
            As[kk][q] = (qi < N1 && ki < N1) ? g_S[Sbase + (size_t)qi * N1 + ki] : 0.f;
        }
        #pragma unroll
        for (int t = 0; t < 16; t++) {
            int idx = tid + t * 256;
            int kk = idx >> 7, j = idx & 127;
            int ki = k0 + kk;
            float v = 0.f;
            if (ki < N1) {
                if (j < 64) v = g_V1[((size_t)b * N1 + ki) * CC + hh * DD + j];
                else        v = g_V2[((size_t)b * N1 + ki) * CC + hh * DD + (j - 64)];
            }
            Vs[kk][j] = v;
        }
        __syncthreads();
        #pragma unroll
        for (int kk = 0; kk < 32; kk++) {
            float a[4], bb[8];
            #pragma unroll
            for (int i = 0; i < 4; i++) a[i] = As[kk][ty * 4 + i];
            #pragma unroll
            for (int j = 0; j < 8; j++) bb[j] = Vs[kk][tx * 8 + j];
            #pragma unroll
            for (int i = 0; i < 4; i++)
                #pragma unroll
                for (int j = 0; j < 8; j++) acc[i][j] += a[i] * bb[j];
        }
        __syncthreads();
    }

    #pragma unroll
    for (int i = 0; i < 4; i++) {
        int qi = q0 + ty * 4 + i;
        if (qi >= N1) continue;
        #pragma unroll
        for (int j = 0; j < 8; j++) {
            int jj = tx * 8 + j;
            int n = (jj < 64) ? qi : (N1 + qi);
            int c = hh * DD + (jj & 63);
            g_O[((size_t)b * M_TOT + n) * CC + c] = acc[i][j];
        }
    }
}

// ------------------------------------------------------------------
// 5) output projection: out = g_O (8208x384) @ Wo + bo
// ------------------------------------------------------------------
__global__ __launch_bounds__(256)
void final_kernel(const float* __restrict__ Wo,
                  const float* __restrict__ bo,
                  float* __restrict__ out) {
    __shared__ float As[32][132];
    __shared__ float Bs[32][64];

    const int m0 = blockIdx.y * 128, n0 = blockIdx.x * 64;
    const int tid = threadIdx.x;
    const int ty = tid >> 4, tx = tid & 15;
    float acc[8][4];
    #pragma unroll
    for (int i = 0; i < 8; i++)
        #pragma unroll
        for (int j = 0; j < 4; j++) acc[i][j] = 0.f;

    for (int k0 = 0; k0 < CC; k0 += 32) {
        #pragma unroll
        for (int t = 0; t < 16; t++) {
            int idx = tid + t * 256;
            int mm = idx >> 5, kk = idx & 31;
            int m = m0 + mm;
            As[kk][mm] = (m < MROWS2) ? g_O[(size_t)m * CC + k0 + kk] : 0.f;
        }
        #pragma unroll
        for (int t = 0; t < 8; t++) {
            int idx = tid + t * 256;
            int kk = idx >> 6, nn = idx & 63;
            Bs[kk][nn] = Wo[(k0 + kk) * CC + n0 + nn];
        }
        __syncthreads();
        #pragma unroll
        for (int kk = 0; kk < 32; kk++) {
            float a[8], bb[4];
            #pragma unroll
            for (int i = 0; i < 8; i++) a[i] = As[kk][ty * 8 + i];
            #pragma unroll
            for (int j = 0; j < 4; j++) bb[j] = Bs[kk][tx * 4 + j];
            #pragma unroll
            for (int i = 0; i < 8; i++)
                #pragma unroll
                for (int j = 0; j < 4; j++) acc[i][j] += a[i] * bb[j];
        }
        __syncthreads();
    }
    #pragma unroll
    for (int i = 0; i < 8; i++) {
        int m = m0 + ty * 8 + i;
        if (m >= MROWS2) continue;
        #pragma unroll
        for (int j = 0; j < 4; j++) {
            int n = n0 + tx * 4 + j;
            out[(size_t)m * CC + n] = acc[i][j] + bo[n];
        }
    }
}

// ------------------------------------------------------------------
extern "C" void kernel_launch(void* const* d_in, const int* in_sizes, int n_in,
                              void* d_out, int out_size) {
    const float* x   = (const float*)d_in[0];
    const float* Wq1 = (const float*)d_in[1];  const float* bq1 = (const float*)d_in[2];
    const float* Wq2 = (const float*)d_in[3];  const float* bq2 = (const float*)d_in[4];
    const float* Wk1 = (const float*)d_in[5];  const float* bk1 = (const float*)d_in[6];
    const float* Wk2 = (const float*)d_in[7];  const float* bk2 = (const float*)d_in[8];
    const float* Wv1 = (const float*)d_in[9];  const float* bv1 = (const float*)d_in[10];
    const float* Wv2 = (const float*)d_in[11]; const float* bv2 = (const float*)d_in[12];
    const float* Wo  = (const float*)d_in[13]; const float* bo  = (const float*)d_in[14];
    const float* wts = (const float*)d_in[15]; const float* gum = (const float*)d_in[16];
    float* out = (float*)d_out;

    select_kernel<<<1, 1>>>(wts, gum);

    dim3 pg(CC / 64, (MROWS + 127) / 128, 4);               // 6 x 33 x 4
    proj_kernel<<<pg, 256>>>(x, Wq1, bq1, Wq2, bq2, Wk1, bk1, Wk2, bk2,
                             Wv1, bv1, Wv2, bv2);

    dim3 sg((N1 + 63) / 64, (N1 + 63) / 64, BHN);           // 9 x 9 x 48
    scores_kernel<<<sg, 256>>>();

    softmax_kernel<<<BHN * N1, 128>>>();

    av_kernel<<<dim3((N1 + 63) / 64, 1, BHN), 256>>>();     // 9 x 1 x 48

    final_kernel<<<dim3(CC / 64, (MROWS2 + 127) / 128, 1), 256>>>(Wo, bo, out);
}